// round 11
// baseline (speedup 1.0000x reference)
#include <cuda_runtime.h>
#include <cstdint>

// Problem capacities (from reference: N=100000, E=1600000, 128->128->64)
#define MAXN 100000
#define MAXE 1600000

// ---------------- scratch (__device__ globals, 256B-aligned for vector ops) --
__device__ __align__(256) float g_deg[MAXN];
__device__ __align__(256) float g_dinv[MAXN];
__device__ __align__(256) int   g_cnt[MAXN];
__device__ __align__(256) int   g_cursor[MAXN];
__device__ __align__(256) int   g_off[MAXN + 2];
__device__ __align__(256) int   g_bsum[1024];
__device__ __align__(256) int   g_boff[1024];
__device__ __align__(256) int2  g_epack[MAXE];            // {src, bits(w*dinv[src])}
__device__ __align__(256) float g_h [(size_t)MAXN * 128]; // x @ W1
__device__ __align__(256) float g_h1[(size_t)MAXN * 128]; // relu(agg1 + b1)
__device__ __align__(256) float g_h2[(size_t)MAXN * 64];  // h1 @ W2

// ---------------- init: deg=1 (self loop), counters=0 -----------------------
__global__ void init_kernel(int n, int e) {
    int i = blockIdx.x * blockDim.x + threadIdx.x;
    if (i == 0) g_off[n] = e;
    if (i < n) {
        g_deg[i] = 1.0f;   // self-loop weight 1
        g_cnt[i] = 0;
        g_cursor[i] = 0;
    }
}

// ---------------- degree + histogram over destination (col) -----------------
// edge_index is int32 (JAX default x64-disabled downcasts jnp.int64 -> int32).
__global__ void hist_kernel(int e, const int* __restrict__ ei,
                            const float* __restrict__ ew) {
    int i = blockIdx.x * blockDim.x + threadIdx.x;
    if (i >= e) return;
    int c = ei[e + i];                         // col = ei[1][i]
    atomicAdd(&g_deg[c], ew[i]);
    atomicAdd(&g_cnt[c], 1);
}

// ---------------- 2-level exclusive scan of g_cnt -> g_off (+ fused dinv) ---
__global__ void scan_partial(int n) {
    __shared__ int s[256];
    int t = threadIdx.x;
    int base = blockIdx.x * 1024;
    int sum = 0;
    for (int i = t; i < 1024; i += 256) {
        int idx = base + i;
        if (idx < n) {
            sum += g_cnt[idx];
            g_dinv[idx] = rsqrtf(g_deg[idx]);  // fused: deg >= 1 always
        }
    }
    s[t] = sum;
    __syncthreads();
    for (int d = 128; d > 0; d >>= 1) {
        if (t < d) s[t] += s[t + d];
        __syncthreads();
    }
    if (t == 0) g_bsum[blockIdx.x] = s[0];
}

__global__ void scan_bsums(int nb) {
    __shared__ int s[1024];
    int t = threadIdx.x;
    int v = (t < nb) ? g_bsum[t] : 0;
    s[t] = v;
    for (int d = 1; d < 1024; d <<= 1) {
        __syncthreads();
        int add = (t >= d) ? s[t - d] : 0;
        __syncthreads();
        s[t] += add;
    }
    if (t < nb) g_boff[t] = s[t] - v;          // exclusive
}

__global__ void scan_final(int n) {
    __shared__ int s[1024];
    int t = threadIdx.x;
    int idx = blockIdx.x * 1024 + t;
    int v = (idx < n) ? g_cnt[idx] : 0;
    s[t] = v;
    for (int d = 1; d < 1024; d <<= 1) {
        __syncthreads();
        int add = (t >= d) ? s[t - d] : 0;
        __syncthreads();
        s[t] += add;
    }
    if (idx < n) g_off[idx] = g_boff[blockIdx.x] + s[t] - v;
}

// ---------------- scatter edges into CSR buckets -----------------------------
__global__ void scatter_kernel(int e, const int* __restrict__ ei,
                               const float* __restrict__ ew) {
    int i = blockIdx.x * blockDim.x + threadIdx.x;
    if (i >= e) return;
    int r = ei[i];
    int c = ei[e + i];
    int pos = g_off[c] + atomicAdd(&g_cursor[c], 1);
    float sw = ew[i] * g_dinv[r];              // w * d_src^{-1/2}
    g_epack[pos] = make_int2(r, __float_as_int(sw));
}

// ---------------- tf32 tensor-core GEMM: Y[n,OC] = X[n,128] @ W[128,OC] ------
__device__ __forceinline__ uint32_t f2tf(float x) {
    uint32_t r;
    asm("cvt.rna.tf32.f32 %0, %1;" : "=r"(r) : "f"(x));
    return r;
}

__device__ __forceinline__ void mma_tf32(float* c, const uint32_t* a,
                                         uint32_t b0, uint32_t b1) {
    asm volatile(
        "mma.sync.aligned.m16n8k8.row.col.f32.tf32.tf32.f32 "
        "{%0,%1,%2,%3}, {%4,%5,%6,%7}, {%8,%9}, {%0,%1,%2,%3};\n"
        : "+f"(c[0]), "+f"(c[1]), "+f"(c[2]), "+f"(c[3])
        : "r"(a[0]), "r"(a[1]), "r"(a[2]), "r"(a[3]), "r"(b0), "r"(b1));
}

// 128 threads (4 warps). Warp owns 32 rows x OC cols. K=128 in chunks of 32.
// Both X and W chunks staged in smem as tf32 (one-time cvt), inner loop is
// pure LDS + HMMA. A-LDS is conflict-free (pad 36: bank = 4g+tg = lane id);
// B-LDS <= 2-way (pad OC+4).
template <int OC>
__device__ __forceinline__ void gemm_tf32_body(int n, const float* __restrict__ X,
                                               const float* __restrict__ W,
                                               float* __restrict__ Y) {
    constexpr int K = 128;
    constexpr int KC = 32;           // k-chunk
    constexpr int XP = KC + 4;       // padded X smem row (36)
    constexpr int OCP = OC + 4;      // padded W smem row
    constexpr int NT = OC / 8;       // n-tiles of 8
    __shared__ __align__(16) uint32_t Ws[KC * OCP];   // 16.9KB (OC=128)
    __shared__ __align__(16) uint32_t Xs[128 * XP];   // 18.4KB

    int tid = threadIdx.x;
    int warp = tid >> 5;
    int lane = tid & 31;
    int g  = lane >> 2;              // 0..7
    int tg = lane & 3;               // 0..3
    int rbase  = blockIdx.x * 128;
    int wrbase = rbase + warp * 32;

    float acc[2][NT][4];
#pragma unroll
    for (int t = 0; t < 2; t++)
#pragma unroll
        for (int nt = 0; nt < NT; nt++)
#pragma unroll
            for (int j = 0; j < 4; j++) acc[t][nt][j] = 0.f;

    for (int kc = 0; kc < K; kc += KC) {
        // stage W chunk [KC][OC] -> tf32 smem
#pragma unroll
        for (int i = tid; i < KC * OC / 4; i += 128) {
            int kk = i / (OC / 4);
            int cc = i % (OC / 4);
            float4 v = reinterpret_cast<const float4*>(W + (size_t)(kc + kk) * OC)[cc];
            uint4 tv = make_uint4(f2tf(v.x), f2tf(v.y), f2tf(v.z), f2tf(v.w));
            *reinterpret_cast<uint4*>(&Ws[kk * OCP + cc * 4]) = tv;
        }
        // stage X chunk [128 rows][KC] -> tf32 smem (coalesced float4, cvt once)
#pragma unroll
        for (int i = tid; i < 128 * KC / 4; i += 128) {
            int rr = i >> 3;                       // row in tile (KC/4 = 8)
            int c4 = i & 7;
            int row = min(rbase + rr, n - 1);      // clamp; stores guarded
            float4 v = reinterpret_cast<const float4*>(X + (size_t)row * K + kc)[c4];
            uint4 tv = make_uint4(f2tf(v.x), f2tf(v.y), f2tf(v.z), f2tf(v.w));
            *reinterpret_cast<uint4*>(&Xs[rr * XP + c4 * 4]) = tv;  // 144rr+16c4: 16B-aligned
        }
        __syncthreads();

#pragma unroll
        for (int ks = 0; ks < KC; ks += 8) {
            uint32_t a[2][4];
#pragma unroll
            for (int t = 0; t < 2; t++) {
                int rA = warp * 32 + t * 16 + g;
                int rB = rA + 8;
                a[t][0] = Xs[rA * XP + ks + tg];
                a[t][1] = Xs[rB * XP + ks + tg];
                a[t][2] = Xs[rA * XP + ks + tg + 4];
                a[t][3] = Xs[rB * XP + ks + tg + 4];
            }
#pragma unroll
            for (int nt = 0; nt < NT; nt++) {
                uint32_t b0 = Ws[(ks + tg)     * OCP + nt * 8 + g];
                uint32_t b1 = Ws[(ks + tg + 4) * OCP + nt * 8 + g];
                mma_tf32(acc[0][nt], a[0], b0, b1);
                mma_tf32(acc[1][nt], a[1], b0, b1);
            }
        }
        __syncthreads();
    }

    // store: c0,c1 at (row g, cols 2tg,2tg+1); c2,c3 at (row g+8)
#pragma unroll
    for (int t = 0; t < 2; t++) {
        int r0 = wrbase + t * 16 + g;
        int r1 = r0 + 8;
#pragma unroll
        for (int nt = 0; nt < NT; nt++) {
            int col = nt * 8 + 2 * tg;
            if (r0 < n)
                *reinterpret_cast<float2*>(Y + (size_t)r0 * OC + col) =
                    make_float2(acc[t][nt][0], acc[t][nt][1]);
            if (r1 < n)
                *reinterpret_cast<float2*>(Y + (size_t)r1 * OC + col) =
                    make_float2(acc[t][nt][2], acc[t][nt][3]);
        }
    }
}

__global__ __launch_bounds__(128) void gemm1_kernel(int n, const float* __restrict__ X,
                                                    const float* __restrict__ W) {
    gemm_tf32_body<128>(n, X, W, g_h);
}

__global__ __launch_bounds__(128) void gemm2_kernel(int n, const float* __restrict__ W) {
    gemm_tf32_body<64>(n, g_h1, W, g_h2);
}

// ---------------- aggregation: out[c] = d_c*(sum sw*h[src] + d_c*h[c]) + b --
// One warp per destination node; gather-only, no atomics.
template <int F, bool RELU>
__device__ __forceinline__ void agg_body(int n, const float* __restrict__ h,
                                         const float* __restrict__ bias,
                                         float* __restrict__ out) {
    int node = blockIdx.x * (blockDim.x >> 5) + (threadIdx.x >> 5);
    if (node >= n) return;
    int lane = threadIdx.x & 31;
    constexpr int V = F / 32;        // 4 (F=128) or 2 (F=64)
    float di = g_dinv[node];

    float acc[V];
    if constexpr (V == 4) {
        float4 hv = *reinterpret_cast<const float4*>(h + (size_t)node * F + lane * 4);
        acc[0] = di * hv.x; acc[1] = di * hv.y; acc[2] = di * hv.z; acc[3] = di * hv.w;
    } else {
        float2 hv = *reinterpret_cast<const float2*>(h + (size_t)node * F + lane * 2);
        acc[0] = di * hv.x; acc[1] = di * hv.y;
    }

    int e0 = g_off[node];
    int e1 = g_off[node + 1];
    int2 p = (e0 < e1) ? g_epack[e0] : make_int2(0, 0);
    for (int e = e0; e < e1; e++) {
        int2 cur = p;
        if (e + 1 < e1) p = g_epack[e + 1];   // prefetch next edge record
        int   r = cur.x;
        float w = __int_as_float(cur.y);
        if constexpr (V == 4) {
            float4 hv = *reinterpret_cast<const float4*>(h + (size_t)r * F + lane * 4);
            acc[0] = fmaf(w, hv.x, acc[0]);
            acc[1] = fmaf(w, hv.y, acc[1]);
            acc[2] = fmaf(w, hv.z, acc[2]);
            acc[3] = fmaf(w, hv.w, acc[3]);
        } else {
            float2 hv = *reinterpret_cast<const float2*>(h + (size_t)r * F + lane * 2);
            acc[0] = fmaf(w, hv.x, acc[0]);
            acc[1] = fmaf(w, hv.y, acc[1]);
        }
    }

#pragma unroll
    for (int v = 0; v < V; v++) {
        float o = fmaf(di, acc[v], bias[lane * V + v]);
        if (RELU) o = fmaxf(o, 0.f);
        out[(size_t)node * F + lane * V + v] = o;
    }
}

__global__ __launch_bounds__(256) void agg1_kernel(int n, const float* __restrict__ b1) {
    agg_body<128, true>(n, g_h, b1, g_h1);
}

__global__ __launch_bounds__(256) void agg2_kernel(int n, const float* __restrict__ b2,
                                                   float* __restrict__ out) {
    agg_body<64, false>(n, g_h2, b2, out);
}

// ---------------- launch (kernel launches ONLY) ------------------------------
extern "C" void kernel_launch(void* const* d_in, const int* in_sizes, int n_in,
                              void* d_out, int out_size) {
    const float* x  = (const float*)d_in[0];
    const int*   ei = (const int*)d_in[1];     // int32 edge_index (JAX x64 off)
    const float* ew = (const float*)d_in[2];
    const float* W1 = (const float*)d_in[3];
    const float* b1 = (const float*)d_in[4];
    const float* W2 = (const float*)d_in[5];
    const float* b2 = (const float*)d_in[6];
    float*       out = (float*)d_out;

    int n = in_sizes[0] / 128;
    int e = in_sizes[2];
    int nb = (n + 1023) / 1024;

    // --- graph preprocessing (deterministic per call) ---
    init_kernel<<<(n + 255) / 256, 256>>>(n, e);
    hist_kernel<<<(e + 255) / 256, 256>>>(e, ei, ew);
    scan_partial<<<nb, 256>>>(n);              // also computes g_dinv
    scan_bsums<<<1, 1024>>>(nb);
    scan_final<<<nb, 1024>>>(n);
    scatter_kernel<<<(e + 255) / 256, 256>>>(e, ei, ew);

    // --- layer 1: h = x@W1 ; h1 = relu(agg(h) + b1) ---
    gemm1_kernel<<<(n + 127) / 128, 128>>>(n, x, W1);
    agg1_kernel<<<(n + 7) / 8, 256>>>(n, b1);

    // --- layer 2: h2 = h1@W2 ; out = agg(h2) + b2 ---
    gemm2_kernel<<<(n + 127) / 128, 128>>>(n, W2);
    agg2_kernel<<<(n + 7) / 8, 256>>>(n, b2, out);
}

// round 12
// speedup vs baseline: 1.2163x; 1.2163x over previous
#include <cuda_runtime.h>
#include <cstdint>

// Problem capacities (from reference: N=100000, E=1600000, 128->128->64)
#define MAXN 100000
#define MAXE 1600000

// ---------------- scratch (__device__ globals, 256B-aligned for vector ops) --
__device__ __align__(256) float g_deg[MAXN];
__device__ __align__(256) float g_dinv[MAXN];
__device__ __align__(256) int   g_cnt[MAXN];
__device__ __align__(256) int   g_cursor[MAXN];
__device__ __align__(256) int   g_off[MAXN + 2];
__device__ __align__(256) int   g_bsum[1024];
__device__ __align__(256) int   g_boff[1024];
__device__ __align__(256) int2  g_epack[MAXE];            // {src, bits(w*dinv[src])}
__device__ __align__(256) float g_h [(size_t)MAXN * 128]; // x @ W1
__device__ __align__(256) float g_h1[(size_t)MAXN * 128]; // relu(agg1 + b1)
__device__ __align__(256) float g_h2[(size_t)MAXN * 64];  // h1 @ W2

// ---------------- init: deg=1 (self loop), counters=0 -----------------------
__global__ void init_kernel(int n, int e) {
    int i = blockIdx.x * blockDim.x + threadIdx.x;
    if (i == 0) g_off[n] = e;
    if (i < n) {
        g_deg[i] = 1.0f;   // self-loop weight 1
        g_cnt[i] = 0;
        g_cursor[i] = 0;
    }
}

// ---------------- degree + histogram over destination (col) -----------------
// edge_index is int32 (JAX default x64-disabled downcasts jnp.int64 -> int32).
__global__ void hist_kernel(int e, const int* __restrict__ ei,
                            const float* __restrict__ ew) {
    int i = blockIdx.x * blockDim.x + threadIdx.x;
    if (i >= e) return;
    int c = ei[e + i];                         // col = ei[1][i]
    atomicAdd(&g_deg[c], ew[i]);
    atomicAdd(&g_cnt[c], 1);
}

// ---------------- scans (shuffle-based) + fused dinv -------------------------
__global__ void scan_partial(int n) {        // 256 thr: block sum of 1024 cnts
    __shared__ int ws[8];
    int t = threadIdx.x;
    int base = blockIdx.x * 1024;
    int sum = 0;
    for (int i = t; i < 1024; i += 256) {
        int idx = base + i;
        if (idx < n) {
            sum += g_cnt[idx];
            g_dinv[idx] = rsqrtf(g_deg[idx]);  // fused: deg >= 1 always
        }
    }
#pragma unroll
    for (int d = 16; d > 0; d >>= 1) sum += __shfl_down_sync(~0u, sum, d);
    if ((t & 31) == 0) ws[t >> 5] = sum;
    __syncthreads();
    if (t < 8) {
        int s = ws[t];
#pragma unroll
        for (int d = 4; d > 0; d >>= 1) s += __shfl_down_sync(0xffu, s, d);
        if (t == 0) g_bsum[blockIdx.x] = s;
    }
}

__global__ void scan_bsums(int nb) {         // 1 block, 1024 thr, excl scan
    __shared__ int ws[32];
    int t = threadIdx.x, lane = t & 31, w = t >> 5;
    int v = (t < nb) ? g_bsum[t] : 0;
    int sc = v;
#pragma unroll
    for (int d = 1; d < 32; d <<= 1) {
        int u = __shfl_up_sync(~0u, sc, d);
        if (lane >= d) sc += u;
    }
    if (lane == 31) ws[w] = sc;
    __syncthreads();
    if (w == 0) {
        int s = ws[lane];
#pragma unroll
        for (int d = 1; d < 32; d <<= 1) {
            int u = __shfl_up_sync(~0u, s, d);
            if (lane >= d) s += u;
        }
        ws[lane] = s;
    }
    __syncthreads();
    int woff = w ? ws[w - 1] : 0;
    if (t < nb) g_boff[t] = woff + sc - v;     // exclusive
}

__global__ void scan_final(int n) {          // 1024 thr/block, excl scan
    __shared__ int ws[32];
    int t = threadIdx.x, lane = t & 31, w = t >> 5;
    int idx = blockIdx.x * 1024 + t;
    int v = (idx < n) ? g_cnt[idx] : 0;
    int sc = v;
#pragma unroll
    for (int d = 1; d < 32; d <<= 1) {
        int u = __shfl_up_sync(~0u, sc, d);
        if (lane >= d) sc += u;
    }
    if (lane == 31) ws[w] = sc;
    __syncthreads();
    if (w == 0) {
        int s = ws[lane];
#pragma unroll
        for (int d = 1; d < 32; d <<= 1) {
            int u = __shfl_up_sync(~0u, s, d);
            if (lane >= d) s += u;
        }
        ws[lane] = s;
    }
    __syncthreads();
    int woff = w ? ws[w - 1] : 0;
    if (idx < n) g_off[idx] = g_boff[blockIdx.x] + woff + sc - v;
}

// ---------------- scatter edges into CSR buckets -----------------------------
__global__ void scatter_kernel(int e, const int* __restrict__ ei,
                               const float* __restrict__ ew) {
    int i = blockIdx.x * blockDim.x + threadIdx.x;
    if (i >= e) return;
    int r = ei[i];
    int c = ei[e + i];
    int pos = g_off[c] + atomicAdd(&g_cursor[c], 1);
    float sw = ew[i] * g_dinv[r];              // w * d_src^{-1/2}
    g_epack[pos] = make_int2(r, __float_as_int(sw));
}

// ---------------- tf32 tensor-core GEMM: Y[n,OC] = X[n,128] @ W[128,OC] ------
__device__ __forceinline__ uint32_t f2tf(float x) {
    uint32_t r;
    asm("cvt.rna.tf32.f32 %0, %1;" : "=r"(r) : "f"(x));
    return r;
}

__device__ __forceinline__ void mma_tf32(float* c, const uint32_t* a,
                                         uint32_t b0, uint32_t b1) {
    asm volatile(
        "mma.sync.aligned.m16n8k8.row.col.f32.tf32.tf32.f32 "
        "{%0,%1,%2,%3}, {%4,%5,%6,%7}, {%8,%9}, {%0,%1,%2,%3};\n"
        : "+f"(c[0]), "+f"(c[1]), "+f"(c[2]), "+f"(c[3])
        : "r"(a[0]), "r"(a[1]), "r"(a[2]), "r"(a[3]), "r"(b0), "r"(b1));
}

// (round-10 version: direct-LDG A operands — measured fastest)
// 128 threads (4 warps). Each warp: 32 rows x OC cols. K=128 in chunks of 32.
template <int OC>
__device__ __forceinline__ void gemm_tf32_body(int n, const float* __restrict__ X,
                                               const float* __restrict__ W,
                                               float* __restrict__ Y) {
    constexpr int K = 128;
    constexpr int KC = 32;           // k-chunk
    constexpr int OCP = OC + 4;      // padded smem row
    constexpr int NT = OC / 8;       // n-tiles of 8
    __shared__ __align__(16) uint32_t Ws[KC * OCP];

    int tid = threadIdx.x;
    int warp = tid >> 5;
    int lane = tid & 31;
    int g  = lane >> 2;              // 0..7
    int tg = lane & 3;               // 0..3
    int rbase = blockIdx.x * 128 + warp * 32;

    float acc[2][NT][4];
#pragma unroll
    for (int t = 0; t < 2; t++)
#pragma unroll
        for (int nt = 0; nt < NT; nt++)
#pragma unroll
            for (int j = 0; j < 4; j++) acc[t][nt][j] = 0.f;

    // clamped A rows (fully-OOB warps read row n-1; stores are guarded)
    int ra[2], rb[2];
#pragma unroll
    for (int t = 0; t < 2; t++) {
        ra[t] = min(rbase + t * 16 + g,     n - 1);
        rb[t] = min(rbase + t * 16 + g + 8, n - 1);
    }

    for (int kc = 0; kc < K; kc += KC) {
        // stage W chunk [KC][OC] -> tf32 smem
        for (int i = tid; i < KC * OC / 4; i += 128) {
            int kk = i / (OC / 4);
            int cc = i % (OC / 4);
            float4 v = reinterpret_cast<const float4*>(W + (size_t)(kc + kk) * OC)[cc];
            uint4 tv = make_uint4(f2tf(v.x), f2tf(v.y), f2tf(v.z), f2tf(v.w));
            *reinterpret_cast<uint4*>(&Ws[kk * OCP + cc * 4]) = tv;
        }
        __syncthreads();

#pragma unroll
        for (int ks = 0; ks < KC; ks += 8) {
            int k0 = kc + ks;
            uint32_t a[2][4];
#pragma unroll
            for (int t = 0; t < 2; t++) {
                a[t][0] = f2tf(X[(size_t)ra[t] * K + k0 + tg]);
                a[t][1] = f2tf(X[(size_t)rb[t] * K + k0 + tg]);
                a[t][2] = f2tf(X[(size_t)ra[t] * K + k0 + tg + 4]);
                a[t][3] = f2tf(X[(size_t)rb[t] * K + k0 + tg + 4]);
            }
#pragma unroll
            for (int nt = 0; nt < NT; nt++) {
                uint32_t b0 = Ws[(ks + tg)     * OCP + nt * 8 + g];
                uint32_t b1 = Ws[(ks + tg + 4) * OCP + nt * 8 + g];
                mma_tf32(acc[0][nt], a[0], b0, b1);
                mma_tf32(acc[1][nt], a[1], b0, b1);
            }
        }
        __syncthreads();
    }

    // store: c0,c1 at (row g, cols 2tg,2tg+1); c2,c3 at (row g+8)
#pragma unroll
    for (int t = 0; t < 2; t++) {
        int r0 = rbase + t * 16 + g;
        int r1 = r0 + 8;
#pragma unroll
        for (int nt = 0; nt < NT; nt++) {
            int col = nt * 8 + 2 * tg;
            if (r0 < n)
                *reinterpret_cast<float2*>(Y + (size_t)r0 * OC + col) =
                    make_float2(acc[t][nt][0], acc[t][nt][1]);
            if (r1 < n)
                *reinterpret_cast<float2*>(Y + (size_t)r1 * OC + col) =
                    make_float2(acc[t][nt][2], acc[t][nt][3]);
        }
    }
}

__global__ __launch_bounds__(128) void gemm1_kernel(int n, const float* __restrict__ X,
                                                    const float* __restrict__ W) {
    gemm_tf32_body<128>(n, X, W, g_h);
}

__global__ __launch_bounds__(128) void gemm2_kernel(int n, const float* __restrict__ W) {
    gemm_tf32_body<64>(n, g_h1, W, g_h2);
}

// ---------------- aggregation: out[c] = d_c*(sum sw*h[src] + d_c*h[c]) + b --
// One warp per destination node; gather-only, no atomics.
template <int F, bool RELU>
__device__ __forceinline__ void agg_body(int n, const float* __restrict__ h,
                                         const float* __restrict__ bias,
                                         float* __restrict__ out) {
    int node = blockIdx.x * (blockDim.x >> 5) + (threadIdx.x >> 5);
    if (node >= n) return;
    int lane = threadIdx.x & 31;
    constexpr int V = F / 32;        // 4 (F=128) or 2 (F=64)
    float di = g_dinv[node];

    float acc[V];
    if constexpr (V == 4) {
        float4 hv = *reinterpret_cast<const float4*>(h + (size_t)node * F + lane * 4);
        acc[0] = di * hv.x; acc[1] = di * hv.y; acc[2] = di * hv.z; acc[3] = di * hv.w;
    } else {
        float2 hv = *reinterpret_cast<const float2*>(h + (size_t)node * F + lane * 2);
        acc[0] = di * hv.x; acc[1] = di * hv.y;
    }

    int e0 = g_off[node];
    int e1 = g_off[node + 1];
    int2 p = (e0 < e1) ? g_epack[e0] : make_int2(0, 0);
    for (int e = e0; e < e1; e++) {
        int2 cur = p;
        if (e + 1 < e1) p = g_epack[e + 1];   // prefetch next edge record
        int   r = cur.x;
        float w = __int_as_float(cur.y);
        if constexpr (V == 4) {
            float4 hv = *reinterpret_cast<const float4*>(h + (size_t)r * F + lane * 4);
            acc[0] = fmaf(w, hv.x, acc[0]);
            acc[1] = fmaf(w, hv.y, acc[1]);
            acc[2] = fmaf(w, hv.z, acc[2]);
            acc[3] = fmaf(w, hv.w, acc[3]);
        } else {
            float2 hv = *reinterpret_cast<const float2*>(h + (size_t)r * F + lane * 2);
            acc[0] = fmaf(w, hv.x, acc[0]);
            acc[1] = fmaf(w, hv.y, acc[1]);
        }
    }

#pragma unroll
    for (int v = 0; v < V; v++) {
        float o = fmaf(di, acc[v], bias[lane * V + v]);
        if (RELU) o = fmaxf(o, 0.f);
        out[(size_t)node * F + lane * V + v] = o;
    }
}

__global__ __launch_bounds__(256) void agg1_kernel(int n, const float* __restrict__ b1) {
    agg_body<128, true>(n, g_h, b1, g_h1);
}

__global__ __launch_bounds__(256) void agg2_kernel(int n, const float* __restrict__ b2,
                                                   float* __restrict__ out) {
    agg_body<64, false>(n, g_h2, b2, out);
}

// ---------------- launch (kernel launches + capture-legal fork/join) ---------
extern "C" void kernel_launch(void* const* d_in, const int* in_sizes, int n_in,
                              void* d_out, int out_size) {
    const float* x  = (const float*)d_in[0];
    const int*   ei = (const int*)d_in[1];     // int32 edge_index (JAX x64 off)
    const float* ew = (const float*)d_in[2];
    const float* W1 = (const float*)d_in[3];
    const float* b1 = (const float*)d_in[4];
    const float* W2 = (const float*)d_in[5];
    const float* b2 = (const float*)d_in[6];
    float*       out = (float*)d_out;

    int n = in_sizes[0] / 128;
    int e = in_sizes[2];
    int nb = (n + 1023) / 1024;

    // one-time handles (no device memory; created on first, non-captured call)
    static cudaStream_t s2 = nullptr;
    static cudaEvent_t ev_fork = nullptr, ev_join = nullptr;
    if (!s2) {
        cudaStreamCreateWithFlags(&s2, cudaStreamNonBlocking);
        cudaEventCreateWithFlags(&ev_fork, cudaEventDisableTiming);
        cudaEventCreateWithFlags(&ev_join, cudaEventDisableTiming);
    }

    // fork: gemm1 (depends only on inputs) runs concurrently with CSR build
    cudaEventRecord(ev_fork, 0);
    cudaStreamWaitEvent(s2, ev_fork, 0);
    gemm1_kernel<<<(n + 127) / 128, 128, 0, s2>>>(n, x, W1);

    // CSR build on origin stream
    init_kernel<<<(n + 255) / 256, 256>>>(n, e);
    hist_kernel<<<(e + 255) / 256, 256>>>(e, ei, ew);
    scan_partial<<<nb, 256>>>(n);              // also computes g_dinv
    scan_bsums<<<1, 1024>>>(nb);
    scan_final<<<nb, 1024>>>(n);
    scatter_kernel<<<(e + 255) / 256, 256>>>(e, ei, ew);

    // join: agg1 needs both CSR and g_h
    cudaEventRecord(ev_join, s2);
    cudaStreamWaitEvent(0, ev_join, 0);

    agg1_kernel<<<(n + 7) / 8, 256>>>(n, b1);
    gemm2_kernel<<<(n + 127) / 128, 128>>>(n, W2);
    agg2_kernel<<<(n + 7) / 8, 256>>>(n, b2, out);
}

// round 13
// speedup vs baseline: 1.3634x; 1.1209x over previous
#include <cuda_runtime.h>
#include <cuda_fp16.h>
#include <cstdint>

// Problem capacities (from reference: N=100000, E=1600000, 128->128->64)
#define MAXN 100000
#define MAXE 1600000

// ---------------- scratch (__device__ globals, 256B-aligned for vector ops) --
__device__ __align__(256) float  g_deg[MAXN];
__device__ __align__(256) float  g_dinv[MAXN];
__device__ __align__(256) int    g_cnt[MAXN];
__device__ __align__(256) int    g_cursor[MAXN];
__device__ __align__(256) int    g_off[MAXN + 2];
__device__ __align__(256) int    g_bsum[1024];
__device__ __align__(256) int    g_boff[1024];
__device__ __align__(256) int2   g_epack[MAXE];             // {src, bits(w*dinv[src])}
__device__ __align__(256) __half g_hH [(size_t)MAXN * 128]; // x @ W1   (fp16)
__device__ __align__(256) float  g_h1 [(size_t)MAXN * 128]; // relu(agg1 + b1) fp32
__device__ __align__(256) __half g_h2H[(size_t)MAXN * 64];  // h1 @ W2  (fp16)

// ---------------- init: deg=1 (self loop), counters=0 -----------------------
__global__ void init_kernel(int n, int e) {
    int i = blockIdx.x * blockDim.x + threadIdx.x;
    if (i == 0) g_off[n] = e;
    if (i < n) {
        g_deg[i] = 1.0f;   // self-loop weight 1
        g_cnt[i] = 0;
        g_cursor[i] = 0;
    }
}

// ---------------- degree + histogram over destination (col) -----------------
// edge_index is int32 (JAX default x64-disabled downcasts jnp.int64 -> int32).
__global__ void hist_kernel(int e, const int* __restrict__ ei,
                            const float* __restrict__ ew) {
    int i = blockIdx.x * blockDim.x + threadIdx.x;
    if (i >= e) return;
    int c = ei[e + i];                         // col = ei[1][i]
    atomicAdd(&g_deg[c], ew[i]);
    atomicAdd(&g_cnt[c], 1);
}

// ---------------- scans (shuffle-based) + fused dinv -------------------------
__global__ void scan_partial(int n) {        // 256 thr: block sum of 1024 cnts
    __shared__ int ws[8];
    int t = threadIdx.x;
    int base = blockIdx.x * 1024;
    int sum = 0;
    for (int i = t; i < 1024; i += 256) {
        int idx = base + i;
        if (idx < n) {
            sum += g_cnt[idx];
            g_dinv[idx] = rsqrtf(g_deg[idx]);  // fused: deg >= 1 always
        }
    }
#pragma unroll
    for (int d = 16; d > 0; d >>= 1) sum += __shfl_down_sync(~0u, sum, d);
    if ((t & 31) == 0) ws[t >> 5] = sum;
    __syncthreads();
    if (t < 8) {
        int s = ws[t];
#pragma unroll
        for (int d = 4; d > 0; d >>= 1) s += __shfl_down_sync(0xffu, s, d);
        if (t == 0) g_bsum[blockIdx.x] = s;
    }
}

__global__ void scan_bsums(int nb) {         // 1 block, 1024 thr, excl scan
    __shared__ int ws[32];
    int t = threadIdx.x, lane = t & 31, w = t >> 5;
    int v = (t < nb) ? g_bsum[t] : 0;
    int sc = v;
#pragma unroll
    for (int d = 1; d < 32; d <<= 1) {
        int u = __shfl_up_sync(~0u, sc, d);
        if (lane >= d) sc += u;
    }
    if (lane == 31) ws[w] = sc;
    __syncthreads();
    if (w == 0) {
        int s = ws[lane];
#pragma unroll
        for (int d = 1; d < 32; d <<= 1) {
            int u = __shfl_up_sync(~0u, s, d);
            if (lane >= d) s += u;
        }
        ws[lane] = s;
    }
    __syncthreads();
    int woff = w ? ws[w - 1] : 0;
    if (t < nb) g_boff[t] = woff + sc - v;     // exclusive
}

__global__ void scan_final(int n) {          // 1024 thr/block, excl scan
    __shared__ int ws[32];
    int t = threadIdx.x, lane = t & 31, w = t >> 5;
    int idx = blockIdx.x * 1024 + t;
    int v = (idx < n) ? g_cnt[idx] : 0;
    int sc = v;
#pragma unroll
    for (int d = 1; d < 32; d <<= 1) {
        int u = __shfl_up_sync(~0u, sc, d);
        if (lane >= d) sc += u;
    }
    if (lane == 31) ws[w] = sc;
    __syncthreads();
    if (w == 0) {
        int s = ws[lane];
#pragma unroll
        for (int d = 1; d < 32; d <<= 1) {
            int u = __shfl_up_sync(~0u, s, d);
            if (lane >= d) s += u;
        }
        ws[lane] = s;
    }
    __syncthreads();
    int woff = w ? ws[w - 1] : 0;
    if (idx < n) g_off[idx] = g_boff[blockIdx.x] + woff + sc - v;
}

// ---------------- scatter edges into CSR buckets -----------------------------
__global__ void scatter_kernel(int e, const int* __restrict__ ei,
                               const float* __restrict__ ew) {
    int i = blockIdx.x * blockDim.x + threadIdx.x;
    if (i >= e) return;
    int r = ei[i];
    int c = ei[e + i];
    int pos = g_off[c] + atomicAdd(&g_cursor[c], 1);
    float sw = ew[i] * g_dinv[r];              // w * d_src^{-1/2}
    g_epack[pos] = make_int2(r, __float_as_int(sw));
}

// ---------------- tf32 tensor-core GEMM: Y[n,OC] = X[n,128] @ W[128,OC] ------
__device__ __forceinline__ uint32_t f2tf(float x) {
    uint32_t r;
    asm("cvt.rna.tf32.f32 %0, %1;" : "=r"(r) : "f"(x));
    return r;
}

__device__ __forceinline__ void mma_tf32(float* c, const uint32_t* a,
                                         uint32_t b0, uint32_t b1) {
    asm volatile(
        "mma.sync.aligned.m16n8k8.row.col.f32.tf32.tf32.f32 "
        "{%0,%1,%2,%3}, {%4,%5,%6,%7}, {%8,%9}, {%0,%1,%2,%3};\n"
        : "+f"(c[0]), "+f"(c[1]), "+f"(c[2]), "+f"(c[3])
        : "r"(a[0]), "r"(a[1]), "r"(a[2]), "r"(a[3]), "r"(b0), "r"(b1));
}

// (round-10 operand path: direct-LDG A — measured fastest)
// 128 threads (4 warps). Each warp: 32 rows x OC cols. K=128 in chunks of 32.
// Output stored as fp16 (half2 pairs: c0,c1 are adjacent cols).
template <int OC>
__device__ __forceinline__ void gemm_tf32_body(int n, const float* __restrict__ X,
                                               const float* __restrict__ W,
                                               __half* __restrict__ Y) {
    constexpr int K = 128;
    constexpr int KC = 32;           // k-chunk
    constexpr int OCP = OC + 4;      // padded smem row
    constexpr int NT = OC / 8;       // n-tiles of 8
    __shared__ __align__(16) uint32_t Ws[KC * OCP];

    int tid = threadIdx.x;
    int warp = tid >> 5;
    int lane = tid & 31;
    int g  = lane >> 2;              // 0..7
    int tg = lane & 3;               // 0..3
    int rbase = blockIdx.x * 128 + warp * 32;

    float acc[2][NT][4];
#pragma unroll
    for (int t = 0; t < 2; t++)
#pragma unroll
        for (int nt = 0; nt < NT; nt++)
#pragma unroll
            for (int j = 0; j < 4; j++) acc[t][nt][j] = 0.f;

    // clamped A rows (fully-OOB warps read row n-1; stores are guarded)
    int ra[2], rb[2];
#pragma unroll
    for (int t = 0; t < 2; t++) {
        ra[t] = min(rbase + t * 16 + g,     n - 1);
        rb[t] = min(rbase + t * 16 + g + 8, n - 1);
    }

    for (int kc = 0; kc < K; kc += KC) {
        // stage W chunk [KC][OC] -> tf32 smem
        for (int i = tid; i < KC * OC / 4; i += 128) {
            int kk = i / (OC / 4);
            int cc = i % (OC / 4);
            float4 v = reinterpret_cast<const float4*>(W + (size_t)(kc + kk) * OC)[cc];
            uint4 tv = make_uint4(f2tf(v.x), f2tf(v.y), f2tf(v.z), f2tf(v.w));
            *reinterpret_cast<uint4*>(&Ws[kk * OCP + cc * 4]) = tv;
        }
        __syncthreads();

#pragma unroll
        for (int ks = 0; ks < KC; ks += 8) {
            int k0 = kc + ks;
            uint32_t a[2][4];
#pragma unroll
            for (int t = 0; t < 2; t++) {
                a[t][0] = f2tf(X[(size_t)ra[t] * K + k0 + tg]);
                a[t][1] = f2tf(X[(size_t)rb[t] * K + k0 + tg]);
                a[t][2] = f2tf(X[(size_t)ra[t] * K + k0 + tg + 4]);
                a[t][3] = f2tf(X[(size_t)rb[t] * K + k0 + tg + 4]);
            }
#pragma unroll
            for (int nt = 0; nt < NT; nt++) {
                uint32_t b0 = Ws[(ks + tg)     * OCP + nt * 8 + g];
                uint32_t b1 = Ws[(ks + tg + 4) * OCP + nt * 8 + g];
                mma_tf32(acc[0][nt], a[0], b0, b1);
                mma_tf32(acc[1][nt], a[1], b0, b1);
            }
        }
        __syncthreads();
    }

    // store fp16: c0,c1 at (row g, cols 2tg,2tg+1); c2,c3 at (row g+8)
#pragma unroll
    for (int t = 0; t < 2; t++) {
        int r0 = rbase + t * 16 + g;
        int r1 = r0 + 8;
#pragma unroll
        for (int nt = 0; nt < NT; nt++) {
            int col = nt * 8 + 2 * tg;
            if (r0 < n)
                *reinterpret_cast<__half2*>(Y + (size_t)r0 * OC + col) =
                    __floats2half2_rn(acc[t][nt][0], acc[t][nt][1]);
            if (r1 < n)
                *reinterpret_cast<__half2*>(Y + (size_t)r1 * OC + col) =
                    __floats2half2_rn(acc[t][nt][2], acc[t][nt][3]);
        }
    }
}

__global__ __launch_bounds__(128) void gemm1_kernel(int n, const float* __restrict__ X,
                                                    const float* __restrict__ W) {
    gemm_tf32_body<128>(n, X, W, g_hH);
}

__global__ __launch_bounds__(128) void gemm2_kernel(int n, const float* __restrict__ W) {
    gemm_tf32_body<64>(n, g_h1, W, g_h2H);
}

// ---------------- aggregation: out[c] = d_c*(sum sw*h[src] + d_c*h[c]) + b --
// One warp per destination node; gather-only, no atomics. h is fp16,
// accumulation fp32. Per-edge warp traffic: 256B (F=128) / 128B (F=64).
template <int F, bool RELU>
__device__ __forceinline__ void agg_body(int n, const __half* __restrict__ h,
                                         const float* __restrict__ bias,
                                         float* __restrict__ out) {
    int node = blockIdx.x * (blockDim.x >> 5) + (threadIdx.x >> 5);
    if (node >= n) return;
    int lane = threadIdx.x & 31;
    constexpr int V = F / 32;        // 4 (F=128) or 2 (F=64)
    float di = g_dinv[node];

    float acc[V];
    if constexpr (V == 4) {
        uint2 raw = reinterpret_cast<const uint2*>(h + (size_t)node * F)[lane];
        float2 f01 = __half22float2(*reinterpret_cast<__half2*>(&raw.x));
        float2 f23 = __half22float2(*reinterpret_cast<__half2*>(&raw.y));
        acc[0] = di * f01.x; acc[1] = di * f01.y;
        acc[2] = di * f23.x; acc[3] = di * f23.y;
    } else {
        __half2 raw = reinterpret_cast<const __half2*>(h + (size_t)node * F)[lane];
        float2 f01 = __half22float2(raw);
        acc[0] = di * f01.x; acc[1] = di * f01.y;
    }

    int e0 = g_off[node];
    int e1 = g_off[node + 1];
    int2 p = (e0 < e1) ? g_epack[e0] : make_int2(0, 0);
    for (int e = e0; e < e1; e++) {
        int2 cur = p;
        if (e + 1 < e1) p = g_epack[e + 1];   // prefetch next edge record
        int   r = cur.x;
        float w = __int_as_float(cur.y);
        if constexpr (V == 4) {
            uint2 raw = reinterpret_cast<const uint2*>(h + (size_t)r * F)[lane];
            float2 f01 = __half22float2(*reinterpret_cast<__half2*>(&raw.x));
            float2 f23 = __half22float2(*reinterpret_cast<__half2*>(&raw.y));
            acc[0] = fmaf(w, f01.x, acc[0]);
            acc[1] = fmaf(w, f01.y, acc[1]);
            acc[2] = fmaf(w, f23.x, acc[2]);
            acc[3] = fmaf(w, f23.y, acc[3]);
        } else {
            __half2 raw = reinterpret_cast<const __half2*>(h + (size_t)r * F)[lane];
            float2 f01 = __half22float2(raw);
            acc[0] = fmaf(w, f01.x, acc[0]);
            acc[1] = fmaf(w, f01.y, acc[1]);
        }
    }

#pragma unroll
    for (int v = 0; v < V; v++) {
        float o = fmaf(di, acc[v], bias[lane * V + v]);
        if (RELU) o = fmaxf(o, 0.f);
        out[(size_t)node * F + lane * V + v] = o;
    }
}

__global__ __launch_bounds__(256) void agg1_kernel(int n, const float* __restrict__ b1) {
    agg_body<128, true>(n, g_hH, b1, g_h1);
}

__global__ __launch_bounds__(256) void agg2_kernel(int n, const float* __restrict__ b2,
                                                   float* __restrict__ out) {
    agg_body<64, false>(n, g_h2H, b2, out);
}

// ---------------- launch (kernel launches + capture-legal fork/join) ---------
extern "C" void kernel_launch(void* const* d_in, const int* in_sizes, int n_in,
                              void* d_out, int out_size) {
    const float* x  = (const float*)d_in[0];
    const int*   ei = (const int*)d_in[1];     // int32 edge_index (JAX x64 off)
    const float* ew = (const float*)d_in[2];
    const float* W1 = (const float*)d_in[3];
    const float* b1 = (const float*)d_in[4];
    const float* W2 = (const float*)d_in[5];
    const float* b2 = (const float*)d_in[6];
    float*       out = (float*)d_out;

    int n = in_sizes[0] / 128;
    int e = in_sizes[2];
    int nb = (n + 1023) / 1024;

    // one-time handles (no device memory; created on first, non-captured call)
    static cudaStream_t s2 = nullptr;
    static cudaEvent_t ev_fork = nullptr, ev_join = nullptr;
    if (!s2) {
        cudaStreamCreateWithFlags(&s2, cudaStreamNonBlocking);
        cudaEventCreateWithFlags(&ev_fork, cudaEventDisableTiming);
        cudaEventCreateWithFlags(&ev_join, cudaEventDisableTiming);
    }

    // fork: gemm1 (depends only on inputs) runs concurrently with CSR build
    cudaEventRecord(ev_fork, 0);
    cudaStreamWaitEvent(s2, ev_fork, 0);
    gemm1_kernel<<<(n + 127) / 128, 128, 0, s2>>>(n, x, W1);

    // CSR build on origin stream
    init_kernel<<<(n + 255) / 256, 256>>>(n, e);
    hist_kernel<<<(e + 255) / 256, 256>>>(e, ei, ew);
    scan_partial<<<nb, 256>>>(n);              // also computes g_dinv
    scan_bsums<<<1, 1024>>>(nb);
    scan_final<<<nb, 1024>>>(n);
    scatter_kernel<<<(e + 255) / 256, 256>>>(e, ei, ew);

    // join: agg1 needs both CSR and g_hH
    cudaEventRecord(ev_join, s2);
    cudaStreamWaitEvent(0, ev_join, 0);

    agg1_kernel<<<(n + 7) / 8, 256>>>(n, b1);
    gemm2_kernel<<<(n + 127) / 128, 128>>>(n, W2);
    agg2_kernel<<<(n + 7) / 8, 256>>>(n, b2, out);
}

// round 14
// speedup vs baseline: 1.3643x; 1.0007x over previous
#include <cuda_runtime.h>
#include <cuda_fp16.h>
#include <cstdint>

// Problem capacities (from reference: N=100000, E=1600000, 128->128->64)
#define MAXN 100000
#define MAXE 1600000

// ---------------- scratch (__device__ globals, 256B-aligned for vector ops) --
__device__ __align__(256) float  g_deg[MAXN];
__device__ __align__(256) float  g_dinv[MAXN];
__device__ __align__(256) int    g_cnt[MAXN];
__device__ __align__(256) int    g_cursor[MAXN];
__device__ __align__(256) int    g_off[MAXN + 2];
__device__ __align__(256) unsigned long long g_bstate[256];  // lookback states
__device__ __align__(256) int2   g_epack[MAXE];             // {src, bits(w*dinv[src])}
__device__ __align__(256) __half g_hH [(size_t)MAXN * 128]; // x @ W1   (fp16)
__device__ __align__(256) float  g_h1 [(size_t)MAXN * 128]; // relu(agg1 + b1) fp32
__device__ __align__(256) __half g_h2H[(size_t)MAXN * 64];  // h1 @ W2  (fp16)

// ---------------- init: deg=1 (self loop), counters=0 -----------------------
__global__ void init_kernel(int n, int e) {
    int i = blockIdx.x * blockDim.x + threadIdx.x;
    if (i == 0) g_off[n] = e;
    if (i < 256) g_bstate[i] = 0ULL;
    if (i < n) {
        g_deg[i] = 1.0f;   // self-loop weight 1
        g_cnt[i] = 0;
        g_cursor[i] = 0;
    }
}

// ---------------- degree + histogram over destination (col) -----------------
// edge_index is int32 (JAX default x64-disabled downcasts jnp.int64 -> int32).
__global__ void hist_kernel(int e, const int* __restrict__ ei,
                            const float* __restrict__ ew) {
    int i = blockIdx.x * blockDim.x + threadIdx.x;
    if (i >= e) return;
    int c = ei[e + i];                         // col = ei[1][i]
    atomicAdd(&g_deg[c], ew[i]);
    atomicAdd(&g_cnt[c], 1);
}

// ---------------- single-pass decoupled-lookback exclusive scan --------------
// 98 blocks x 256 thr; 1024 elements/block. All blocks fit in one wave
// (98 <= 148 SMs) so the lookback spin always makes forward progress.
// Also fuses dinv = rsqrt(deg).
__global__ __launch_bounds__(256) void scan_lookback(int n) {
    __shared__ int wsum[8];
    __shared__ int s_prefix;
    int t = threadIdx.x, lane = t & 31, w = t >> 5;
    int bid = blockIdx.x;
    int base = bid * 1024 + t * 4;

    int v[4];
#pragma unroll
    for (int j = 0; j < 4; j++) {
        int idx = base + j;
        if (idx < n) {
            v[j] = g_cnt[idx];
            g_dinv[idx] = rsqrtf(g_deg[idx]);  // fused: deg >= 1 always
        } else v[j] = 0;
    }
    int tsum = v[0] + v[1] + v[2] + v[3];

    // warp inclusive scan of per-thread sums
    int sc = tsum;
#pragma unroll
    for (int d = 1; d < 32; d <<= 1) {
        int u = __shfl_up_sync(~0u, sc, d);
        if (lane >= d) sc += u;
    }
    if (lane == 31) wsum[w] = sc;
    __syncthreads();
    if (w == 0) {
        int s = (lane < 8) ? wsum[lane] : 0;
#pragma unroll
        for (int d = 1; d < 8; d <<= 1) {
            int u = __shfl_up_sync(~0u, s, d);
            if (lane >= d) s += u;
        }
        if (lane < 8) wsum[lane] = s;       // inclusive scan of warp sums
    }
    __syncthreads();
    int total = wsum[7];

    if (t == 0) {
        if (bid == 0) {
            atomicExch(&g_bstate[0], (2ULL << 32) | (unsigned)total);
            s_prefix = 0;
        } else {
            atomicExch(&g_bstate[bid], (1ULL << 32) | (unsigned)total);
            int pre = 0;
            int p = bid - 1;
            while (p >= 0) {
                unsigned long long st = atomicAdd(&g_bstate[p], 0ULL);
                unsigned flag = (unsigned)(st >> 32);
                if (flag == 0) continue;         // spin: predecessor pending
                pre += (int)(unsigned)st;
                if (flag == 2) break;            // inclusive prefix found
                p--;
            }
            atomicExch(&g_bstate[bid], (2ULL << 32) | (unsigned)(pre + total));
            s_prefix = pre;
        }
    }
    __syncthreads();

    int run = s_prefix + ((w > 0) ? wsum[w - 1] : 0) + (sc - tsum);
#pragma unroll
    for (int j = 0; j < 4; j++) {
        int idx = base + j;
        if (idx < n) g_off[idx] = run;
        run += v[j];
    }
}

// ---------------- scatter edges into CSR buckets -----------------------------
__global__ void scatter_kernel(int e, const int* __restrict__ ei,
                               const float* __restrict__ ew) {
    int i = blockIdx.x * blockDim.x + threadIdx.x;
    if (i >= e) return;
    int r = ei[i];
    int c = ei[e + i];
    int pos = g_off[c] + atomicAdd(&g_cursor[c], 1);
    float sw = ew[i] * g_dinv[r];              // w * d_src^{-1/2}
    g_epack[pos] = make_int2(r, __float_as_int(sw));
}

// ---------------- tf32 tensor-core GEMM: Y[n,OC] = X[n,128] @ W[128,OC] ------
__device__ __forceinline__ uint32_t f2tf(float x) {
    uint32_t r;
    asm("cvt.rna.tf32.f32 %0, %1;" : "=r"(r) : "f"(x));
    return r;
}

__device__ __forceinline__ void mma_tf32(float* c, const uint32_t* a,
                                         uint32_t b0, uint32_t b1) {
    asm volatile(
        "mma.sync.aligned.m16n8k8.row.col.f32.tf32.tf32.f32 "
        "{%0,%1,%2,%3}, {%4,%5,%6,%7}, {%8,%9}, {%0,%1,%2,%3};\n"
        : "+f"(c[0]), "+f"(c[1]), "+f"(c[2]), "+f"(c[3])
        : "r"(a[0]), "r"(a[1]), "r"(a[2]), "r"(a[3]), "r"(b0), "r"(b1));
}

// (round-10 operand path: direct-LDG A — measured fastest)
// 128 threads (4 warps). Each warp: 32 rows x OC cols. K=128 in chunks of 32.
// Output stored as fp16 (half2 pairs: c0,c1 are adjacent cols).
template <int OC>
__device__ __forceinline__ void gemm_tf32_body(int n, const float* __restrict__ X,
                                               const float* __restrict__ W,
                                               __half* __restrict__ Y) {
    constexpr int K = 128;
    constexpr int KC = 32;           // k-chunk
    constexpr int OCP = OC + 4;      // padded smem row
    constexpr int NT = OC / 8;       // n-tiles of 8
    __shared__ __align__(16) uint32_t Ws[KC * OCP];

    int tid = threadIdx.x;
    int warp = tid >> 5;
    int lane = tid & 31;
    int g  = lane >> 2;              // 0..7
    int tg = lane & 3;               // 0..3
    int rbase = blockIdx.x * 128 + warp * 32;

    float acc[2][NT][4];
#pragma unroll
    for (int t = 0; t < 2; t++)
#pragma unroll
        for (int nt = 0; nt < NT; nt++)
#pragma unroll
            for (int j = 0; j < 4; j++) acc[t][nt][j] = 0.f;

    // clamped A rows (fully-OOB warps read row n-1; stores are guarded)
    int ra[2], rb[2];
#pragma unroll
    for (int t = 0; t < 2; t++) {
        ra[t] = min(rbase + t * 16 + g,     n - 1);
        rb[t] = min(rbase + t * 16 + g + 8, n - 1);
    }

    for (int kc = 0; kc < K; kc += KC) {
        // stage W chunk [KC][OC] -> tf32 smem
        for (int i = tid; i < KC * OC / 4; i += 128) {
            int kk = i / (OC / 4);
            int cc = i % (OC / 4);
            float4 v = reinterpret_cast<const float4*>(W + (size_t)(kc + kk) * OC)[cc];
            uint4 tv = make_uint4(f2tf(v.x), f2tf(v.y), f2tf(v.z), f2tf(v.w));
            *reinterpret_cast<uint4*>(&Ws[kk * OCP + cc * 4]) = tv;
        }
        __syncthreads();

#pragma unroll
        for (int ks = 0; ks < KC; ks += 8) {
            int k0 = kc + ks;
            uint32_t a[2][4];
#pragma unroll
            for (int t = 0; t < 2; t++) {
                a[t][0] = f2tf(X[(size_t)ra[t] * K + k0 + tg]);
                a[t][1] = f2tf(X[(size_t)rb[t] * K + k0 + tg]);
                a[t][2] = f2tf(X[(size_t)ra[t] * K + k0 + tg + 4]);
                a[t][3] = f2tf(X[(size_t)rb[t] * K + k0 + tg + 4]);
            }
#pragma unroll
            for (int nt = 0; nt < NT; nt++) {
                uint32_t b0 = Ws[(ks + tg)     * OCP + nt * 8 + g];
                uint32_t b1 = Ws[(ks + tg + 4) * OCP + nt * 8 + g];
                mma_tf32(acc[0][nt], a[0], b0, b1);
                mma_tf32(acc[1][nt], a[1], b0, b1);
            }
        }
        __syncthreads();
    }

    // store fp16: c0,c1 at (row g, cols 2tg,2tg+1); c2,c3 at (row g+8)
#pragma unroll
    for (int t = 0; t < 2; t++) {
        int r0 = rbase + t * 16 + g;
        int r1 = r0 + 8;
#pragma unroll
        for (int nt = 0; nt < NT; nt++) {
            int col = nt * 8 + 2 * tg;
            if (r0 < n)
                *reinterpret_cast<__half2*>(Y + (size_t)r0 * OC + col) =
                    __floats2half2_rn(acc[t][nt][0], acc[t][nt][1]);
            if (r1 < n)
                *reinterpret_cast<__half2*>(Y + (size_t)r1 * OC + col) =
                    __floats2half2_rn(acc[t][nt][2], acc[t][nt][3]);
        }
    }
}

__global__ __launch_bounds__(128) void gemm1_kernel(int n, const float* __restrict__ X,
                                                    const float* __restrict__ W) {
    gemm_tf32_body<128>(n, X, W, g_hH);
}

__global__ __launch_bounds__(128) void gemm2_kernel(int n, const float* __restrict__ W) {
    gemm_tf32_body<64>(n, g_h1, W, g_h2H);
}

// ---------------- aggregation: out[c] = d_c*(sum sw*h[src] + d_c*h[c]) + b --
// One warp per destination node; gather-only, no atomics. h is fp16,
// fp32 accumulate. Edge loop unrolled x2 (two independent gathers in flight).
template <int F, bool RELU>
__device__ __forceinline__ void agg_body(int n, const __half* __restrict__ h,
                                         const float* __restrict__ bias,
                                         float* __restrict__ out) {
    int node = blockIdx.x * (blockDim.x >> 5) + (threadIdx.x >> 5);
    if (node >= n) return;
    int lane = threadIdx.x & 31;
    constexpr int V = F / 32;        // 4 (F=128) or 2 (F=64)
    float di = g_dinv[node];

    float acc[V];
    if constexpr (V == 4) {
        uint2 raw = reinterpret_cast<const uint2*>(h + (size_t)node * F)[lane];
        float2 f01 = __half22float2(*reinterpret_cast<__half2*>(&raw.x));
        float2 f23 = __half22float2(*reinterpret_cast<__half2*>(&raw.y));
        acc[0] = di * f01.x; acc[1] = di * f01.y;
        acc[2] = di * f23.x; acc[3] = di * f23.y;
    } else {
        __half2 raw = reinterpret_cast<const __half2*>(h + (size_t)node * F)[lane];
        float2 f01 = __half22float2(raw);
        acc[0] = di * f01.x; acc[1] = di * f01.y;
    }

    int e0 = g_off[node];
    int e1 = g_off[node + 1];
    int e = e0;
    for (; e + 2 <= e1; e += 2) {              // x2: two independent gathers
        int2 p0 = g_epack[e];
        int2 p1 = g_epack[e + 1];
        float w0 = __int_as_float(p0.y);
        float w1 = __int_as_float(p1.y);
        if constexpr (V == 4) {
            uint2 r0 = reinterpret_cast<const uint2*>(h + (size_t)p0.x * F)[lane];
            uint2 r1 = reinterpret_cast<const uint2*>(h + (size_t)p1.x * F)[lane];
            float2 a01 = __half22float2(*reinterpret_cast<__half2*>(&r0.x));
            float2 a23 = __half22float2(*reinterpret_cast<__half2*>(&r0.y));
            float2 b01 = __half22float2(*reinterpret_cast<__half2*>(&r1.x));
            float2 b23 = __half22float2(*reinterpret_cast<__half2*>(&r1.y));
            acc[0] = fmaf(w0, a01.x, acc[0]); acc[1] = fmaf(w0, a01.y, acc[1]);
            acc[2] = fmaf(w0, a23.x, acc[2]); acc[3] = fmaf(w0, a23.y, acc[3]);
            acc[0] = fmaf(w1, b01.x, acc[0]); acc[1] = fmaf(w1, b01.y, acc[1]);
            acc[2] = fmaf(w1, b23.x, acc[2]); acc[3] = fmaf(w1, b23.y, acc[3]);
        } else {
            __half2 r0 = reinterpret_cast<const __half2*>(h + (size_t)p0.x * F)[lane];
            __half2 r1 = reinterpret_cast<const __half2*>(h + (size_t)p1.x * F)[lane];
            float2 a01 = __half22float2(r0);
            float2 b01 = __half22float2(r1);
            acc[0] = fmaf(w0, a01.x, acc[0]); acc[1] = fmaf(w0, a01.y, acc[1]);
            acc[0] = fmaf(w1, b01.x, acc[0]); acc[1] = fmaf(w1, b01.y, acc[1]);
        }
    }
    if (e < e1) {                              // tail edge
        int2 p0 = g_epack[e];
        float w0 = __int_as_float(p0.y);
        if constexpr (V == 4) {
            uint2 r0 = reinterpret_cast<const uint2*>(h + (size_t)p0.x * F)[lane];
            float2 a01 = __half22float2(*reinterpret_cast<__half2*>(&r0.x));
            float2 a23 = __half22float2(*reinterpret_cast<__half2*>(&r0.y));
            acc[0] = fmaf(w0, a01.x, acc[0]); acc[1] = fmaf(w0, a01.y, acc[1]);
            acc[2] = fmaf(w0, a23.x, acc[2]); acc[3] = fmaf(w0, a23.y, acc[3]);
        } else {
            __half2 r0 = reinterpret_cast<const __half2*>(h + (size_t)p0.x * F)[lane];
            float2 a01 = __half22float2(r0);
            acc[0] = fmaf(w0, a01.x, acc[0]); acc[1] = fmaf(w0, a01.y, acc[1]);
        }
    }

#pragma unroll
    for (int v = 0; v < V; v++) {
        float o = fmaf(di, acc[v], bias[lane * V + v]);
        if (RELU) o = fmaxf(o, 0.f);
        out[(size_t)node * F + lane * V + v] = o;
    }
}

__global__ __launch_bounds__(256) void agg1_kernel(int n, const float* __restrict__ b1) {
    agg_body<128, true>(n, g_hH, b1, g_h1);
}

__global__ __launch_bounds__(256) void agg2_kernel(int n, const float* __restrict__ b2,
                                                   float* __restrict__ out) {
    agg_body<64, false>(n, g_h2H, b2, out);
}

// ---------------- launch (kernel launches + capture-legal fork/join) ---------
extern "C" void kernel_launch(void* const* d_in, const int* in_sizes, int n_in,
                              void* d_out, int out_size) {
    const float* x  = (const float*)d_in[0];
    const int*   ei = (const int*)d_in[1];     // int32 edge_index (JAX x64 off)
    const float* ew = (const float*)d_in[2];
    const float* W1 = (const float*)d_in[3];
    const float* b1 = (const float*)d_in[4];
    const float* W2 = (const float*)d_in[5];
    const float* b2 = (const float*)d_in[6];
    float*       out = (float*)d_out;

    int n = in_sizes[0] / 128;
    int e = in_sizes[2];
    int nb = (n + 1023) / 1024;

    // one-time handles (no device memory; created on first, non-captured call)
    static cudaStream_t s2 = nullptr;
    static cudaEvent_t ev_fork = nullptr, ev_join = nullptr;
    if (!s2) {
        cudaStreamCreateWithFlags(&s2, cudaStreamNonBlocking);
        cudaEventCreateWithFlags(&ev_fork, cudaEventDisableTiming);
        cudaEventCreateWithFlags(&ev_join, cudaEventDisableTiming);
    }

    // fork: gemm1 (depends only on inputs) runs concurrently with CSR build
    cudaEventRecord(ev_fork, 0);
    cudaStreamWaitEvent(s2, ev_fork, 0);
    gemm1_kernel<<<(n + 127) / 128, 128, 0, s2>>>(n, x, W1);

    // CSR build on origin stream
    init_kernel<<<(n + 255) / 256, 256>>>(n, e);
    hist_kernel<<<(e + 255) / 256, 256>>>(e, ei, ew);
    scan_lookback<<<nb, 256>>>(n);             // single-pass scan + dinv
    scatter_kernel<<<(e + 255) / 256, 256>>>(e, ei, ew);

    // join: agg1 needs both CSR and g_hH
    cudaEventRecord(ev_join, s2);
    cudaStreamWaitEvent(0, ev_join, 0);

    agg1_kernel<<<(n + 7) / 8, 256>>>(n, b1);
    gemm2_kernel<<<(n + 127) / 128, 128>>>(n, W2);
    agg2_kernel<<<(n + 7) / 8, 256>>>(n, b2, out);
}